// round 7
// baseline (speedup 1.0000x reference)
#include <cuda_runtime.h>
#include <cuda_bf16.h>

#define NS      65536
#define NRES    16
#define NOSC    16
#define NCPD    16
#define WIN     2048
#define FRAMES  512
#define DEFF    256
#define RE      32            // NRES*NEXPR
#define ORE     512           // NOSC*NRES*NEXPR
#define OB      65536         // out offset: before_upsample
#define OC      73728         // out offset: cs
#define DELTA   (10.0f/65535.0f)
#define HEAD    3072          // direct-FIR head length (>= 2057, mult of 1024)
#define RESN    4096          // samples of d_res actually materialized (gfir reach)

// ----------------------------- device scratch --------------------------------
__device__ float d_xd[ORE], d_om[ORE], d_phi[ORE], d_aa[ORE], d_am[ORE];
__device__ float d_sc[ORE], d_sn[ORE], d_ed[ORE];   // per-mode step cos/sin, env step
__device__ int   d_nco[ORE];
__device__ int   d_Lg[RE], d_ncm[RE];
__device__ float d_routed[NRES*FRAMES];
__device__ float d_imp[NCPD*WIN];
__device__ float d_dsm[2*DEFF];
__device__ float d_m0[NRES], d_m1[NRES], d_ga[NRES];
__device__ float d_res[RE*RESN];   // un-normalized resonances, head only (zero elsewhere)
__device__ float d_ssp[RE*256];    // sum-of-squares partials
__device__ float d_Pr[ORE], d_Pi[ORE];   // modal prefactors for g (UNscaled by ninv)
__device__ float d_g[RE*NS];       // g = (imp (*) res_normalized)

// ------------------- K1: params, softmaxes, impulse, routing -----------------
__global__ void k_setup(const float* __restrict__ ctrl,  const float* __restrict__ defo,
                        const float* __restrict__ noise, const float* __restrict__ attack,
                        const float* __restrict__ router,const float* __restrict__ mixp,
                        const float* __restrict__ gains, const float* __restrict__ damping,
                        const float* __restrict__ mass,  const float* __restrict__ tension,
                        const float* __restrict__ idisp, const float* __restrict__ amps,
                        float* __restrict__ out, int out_size)
{
    int b = blockIdx.x, tid = threadIdx.x;
    if (b == 0) {
        // one thread per (osc,res,expr); flat idx = o*32 + r*2 + e
        __shared__ int snc[ORE];
        int idx = tid;
        float m   = 1.0f / (1.0f + expf(-mass[idx]));
        float dmp = (1.0f / (1.0f + expf(-damping[idx]))) * 30.0f;
        float ten = exp10f(tension[idx]);
        float x0  = idisp[idx];
        float xd  = dmp / (2.0f * m);
        float om2 = fmaxf(__fsub_rn(ten, __fmul_rn(xd, xd)), 1e-12f);
        float om  = sqrtf(om2);
        float phi = atan2f(__fmul_rn(xd, x0), __fmul_rn(x0, om));
        float a   = x0 / cosf(phi);
        float amp = amps[idx];
        float amp2 = __fmul_rn(amp, amp);
        d_xd[idx] = xd; d_om[idx] = om; d_phi[idx] = phi; d_aa[idx] = a; d_am[idx] = amp2;
        // rotation constants for the modal tail (double-accurate step)
        double bd = (double)om * (10.0 / 65535.0);
        d_sc[idx] = (float)cos(bd);
        d_sn[idx] = (float)sin(bd);
        d_ed[idx] = expf(-xd * DELTA);
        // truncation: coef*exp(-xd*t) < coef*e^-34 beyond tcut -> negligible
        float coef = fabsf(a) * amp2;
        float tcut = (logf(coef + 1e-30f) + 34.0f) / xd;
        int nc = (tcut <= 0.0f) ? 0 : (int)(tcut / DELTA) + 2;
        nc = min(nc, NS);
        d_nco[idx] = nc;
        snc[idx] = nc;
        __syncthreads();
        if (tid < RE) {
            int mx = 0;
            #pragma unroll
            for (int o = 0; o < NOSC; ++o) mx = max(mx, snc[o*RE + tid]);
            d_ncm[tid] = mx;
            d_Lg[tid]  = min(mx + WIN, NS);
        }
    } else if (b == 1) {
        if (tid < DEFF) {
            float v0 = 1.0f + defo[tid];
            float v1 = defo[DEFF + tid];
            float mx = fmaxf(v0, v1);
            float e0 = expf(v0 - mx), e1 = expf(v1 - mx);
            float inv = 1.0f / (e0 + e1);
            d_dsm[tid]        = e0 * inv;
            d_dsm[DEFF + tid] = e1 * inv;
        } else if (tid < DEFF + NRES) {
            int r = tid - DEFF;
            float a0 = mixp[r*2], a1 = mixp[r*2+1];
            float mx = fmaxf(a0, a1);
            float e0 = expf(a0 - mx), e1 = expf(a1 - mx);
            float inv = 1.0f / (e0 + e1);
            d_m0[r] = e0 * inv; d_m1[r] = e1 * inv;
            d_ga[r] = fabsf(gains[r]);
        }
    } else if (b < 66) {
        int i = (b - 2) * 512 + tid;                 // 0..32767
        d_imp[i] = attack[i] * noise[i];
    } else {
        int i = (b - 66) * 512 + tid;                // 0..8191
        int r = i >> 9, f = i & 511;
        float acc = 0.0f;
        #pragma unroll
        for (int c = 0; c < NCPD; ++c)
            acc = fmaf(ctrl[c*FRAMES + f], router[c*NRES + r], acc);
        d_routed[i] = acc;
        if (OB + i < out_size) out[OB + i] = acc;    // before_upsample output
    }
}

// ---- K2: (fused) resonances + SS partials  AND  modal prefactors ------------
__global__ void __launch_bounds__(256) k_respref()
{
    int tid = threadIdx.x;

    if (blockIdx.x >= 256) {
        // ---------------- prefactor part: one block per mode ----------------
        int w  = (blockIdx.x - 256) * 32 + blockIdx.y;   // mode 0..511
        int r  = (w & 31) >> 1;

        __shared__ float sb12, sbrest, sstepc, ssteps;
        if (tid == 0) {
            double beta_d = (double)d_om[w] * (10.0 / 65535.0);
            float b12 = __int_as_float(__float_as_int((float)beta_d) & 0xFFFFF000u);
            sb12   = b12;
            sbrest = (float)(beta_d - (double)b12);
            sstepc = (float)cos(beta_d);
            ssteps = (float)sin(beta_d);
        }
        __syncthreads();

        float xd = d_xd[w];
        float b12 = sb12, brest = sbrest, stepc = sstepc, steps = ssteps;

        const double TPd = 6.283185307179586476925287;
        const float  TPH = 6.28125f;
        const float  TPM = (float)(TPd - (double)TPH);
        const float  TPL = (float)(TPd - (double)TPH - (double)(float)(TPd - (double)TPH));
        const float  INV2PI = 0.15915494309189535f;

        int   k0 = tid * 8;
        float kf = (float)k0;
        float phi0 = kf * b12;                        // exact (8+12 mantissa bits)
        float qq = rintf(phi0 * INV2PI);
        float rp = fmaf(-qq, TPH, phi0);
        rp = fmaf(-qq, TPM, rp);
        rp = fmaf(-qq, TPL, rp);
        rp = fmaf(kf, brest, rp);
        float c, s;
        sincosf(rp, &s, &c);
        float env = expf(-xd * (kf * DELTA));
        float ef  = expf(-xd * DELTA);

        const float* impr = d_imp + r*WIN + (2047 - k0);
        float fr = 0.f, fi = 0.f;
        #pragma unroll
        for (int j = 0; j < 8; ++j) {
            float wgt = impr[-j] * env;
            fr = fmaf(wgt, c, fr);
            fi = fmaf(wgt, s, fi);
            float c2 = c*stepc - s*steps;
            float s2 = c*steps + s*stepc;
            c = c2; s = s2;
            env *= ef;
        }

        double sr = (double)fr, si = (double)fi;
        #pragma unroll
        for (int off = 16; off; off >>= 1) {
            sr += __shfl_down_sync(0xffffffffu, sr, off);
            si += __shfl_down_sync(0xffffffffu, si, off);
        }
        __shared__ double redr[8], redi[8];
        int wi = tid >> 5, lane = tid & 31;
        if (lane == 0) { redr[wi] = sr; redi[wi] = si; }
        __syncthreads();
        if (tid == 0) {
            double Sr = 0.0, Si = 0.0;
            #pragma unroll
            for (int i = 0; i < 8; ++i) { Sr += redr[i]; Si += redi[i]; }
            float phi = d_phi[w];
            float a   = d_aa[w], am = d_am[w];
            float cp = cosf(phi), sp = sinf(phi);
            float Ar =  a * am * cp;
            float Ai = -a * am * sp;          // A = a*amp^2 * e^{-i phi}
            float Cr = (float)Sr, Ci = (float)Si;
            d_Pr[w] = (Ar*Cr - Ai*Ci);        // unscaled; ninv applied downstream
            d_Pi[w] = (Ar*Ci + Ai*Cr);
        }
        return;
    }

    // -------------------- resonance part (blocks 0..255) ---------------------
    int re = blockIdx.y;
    int n  = blockIdx.x * 256 + tid;

    if (blockIdx.x * 256 >= d_ncm[re]) {             // whole block past all cutoffs
        if (tid == 0) d_ssp[re*256 + blockIdx.x] = 0.0f;
        return;
    }

    __shared__ float sxd[NOSC], som[NOSC], sphi[NOSC], sa[NOSC], sam[NOSC];
    __shared__ int   snc[NOSC];
    if (tid < NOSC) {
        int idx = tid * RE + re;
        sxd[tid] = d_xd[idx]; som[tid] = d_om[idx]; sphi[tid] = d_phi[idx];
        sa[tid]  = d_aa[idx]; sam[tid] = d_am[idx]; snc[tid]  = d_nco[idx];
    }
    __syncthreads();

    float t = __fmul_rn((float)n, DELTA);
    float acc = 0.0f;
    #pragma unroll
    for (int o = 0; o < NOSC; ++o) {
        if (n < snc[o]) {
            float env = expf(-__fmul_rn(sxd[o], t));
            float arg = __fsub_rn(__fmul_rn(som[o], t), sphi[o]);  // match ref rounding
            float z   = __fmul_rn(__fmul_rn(sa[o], env), cosf(arg));
            acc = __fadd_rn(acc, __fmul_rn(z, sam[o]));
        }
    }
    if (n < 10) acc = __fmul_rn(acc, __fmul_rn((float)n, 1.0f/9.0f));   // ramp
    if (blockIdx.x < RESN/256) d_res[re*RESN + n] = acc;   // only the FIR head is read

    __shared__ float red[256];
    red[tid] = acc * acc;
    __syncthreads();
    for (int s = 128; s > 0; s >>= 1) {
        if (tid < s) red[tid] += red[tid + s];
        __syncthreads();
    }
    if (tid == 0) d_ssp[re*256 + blockIdx.x] = red[0];
}

// ---- K3: g materialization (FIR head + modal tail), norm inlined ------------
__global__ void __launch_bounds__(256) k_g()
{
    int re  = blockIdx.y;
    int tid = threadIdx.x;
    int T0  = blockIdx.x * 1024;
    int Lg  = d_Lg[re];
    float* gout = d_g + re*NS + T0;

    if (T0 >= Lg) {                      // g numerically zero here
        #pragma unroll
        for (int k = 0; k < 4; ++k) gout[tid + k*256] = 0.0f;
        return;
    }

    // inline norm: reduce 256 SS partials -> ninv
    __shared__ float nred[256];
    __shared__ float sninv;
    nred[tid] = d_ssp[re*256 + tid];
    __syncthreads();
    for (int s = 128; s > 0; s >>= 1) {
        if (tid < s) nred[tid] += nred[tid + s];
        __syncthreads();
    }
    if (tid == 0) sninv = 1.0f / (sqrtf(nred[0]) + 1e-8f);
    __syncthreads();
    float ninv = sninv;

    if (blockIdx.x < HEAD/1024) {
        // -------- direct FIR head --------
        int r = re >> 1;
        __shared__ float imp_s[WIN];
        __shared__ float res_s[3072];
        for (int i = tid; i < WIN; i += 256) imp_s[i] = d_imp[r*WIN + i];
        for (int i = tid; i < 3072; i += 256) {
            int gi = T0 - 2047 + i;
            res_s[i] = (gi >= 0) ? d_res[re*RESN + gi] : 0.0f;
        }
        __syncthreads();

        int t0l = tid * 4;
        float a0 = 0.f, a1 = 0.f, a2 = 0.f, a3 = 0.f;
        #pragma unroll 8
        for (int j = 0; j < WIN; ++j) {
            float ij = imp_s[j];
            int bi = 2047 + t0l - j;
            a0 = fmaf(ij, res_s[bi    ], a0);
            a1 = fmaf(ij, res_s[bi + 1], a1);
            a2 = fmaf(ij, res_s[bi + 2], a2);
            a3 = fmaf(ij, res_s[bi + 3], a3);
        }
        gout[t0l    ] = a0 * ninv;
        gout[t0l + 1] = a1 * ninv;
        gout[t0l + 2] = a2 * ninv;
        gout[t0l + 3] = a3 * ninv;
    } else {
        // -------- modal tail: 4 consecutive samples per thread, rotation ----
        __shared__ float sxd[NOSC], som[NOSC], spr[NOSC], spi[NOSC];
        __shared__ float ssc[NOSC], ssn[NOSC], sed[NOSC];
        if (tid < NOSC) {
            int idx = tid * RE + re;
            sxd[tid] = d_xd[idx]; som[tid] = d_om[idx];
            spr[tid] = d_Pr[idx]; spi[tid] = d_Pi[idx];
            ssc[tid] = d_sc[idx]; ssn[tid] = d_sn[idx]; sed[tid] = d_ed[idx];
        }
        __syncthreads();

        int n0 = T0 + tid * 4;
        float tau0 = __fmul_rn((float)(n0 - 2047), DELTA);
        float acc0 = 0.f, acc1 = 0.f, acc2 = 0.f, acc3 = 0.f;
        #pragma unroll
        for (int o = 0; o < NOSC; ++o) {
            float s0, c0;
            sincosf(som[o] * tau0, &s0, &c0);
            float env = expf(-sxd[o] * tau0);
            float pr = spr[o], pi = spi[o];
            float sc = ssc[o], sn = ssn[o], ed = sed[o];
            acc0 = fmaf(env, pr*c0 - pi*s0, acc0);
            float c1 = c0*sc - s0*sn, s1 = c0*sn + s0*sc; env *= ed;
            acc1 = fmaf(env, pr*c1 - pi*s1, acc1);
            float c2 = c1*sc - s1*sn, s2 = c1*sn + s1*sc; env *= ed;
            acc2 = fmaf(env, pr*c2 - pi*s2, acc2);
            float c3 = c2*sc - s2*sn, s3 = c2*sn + s2*sc; env *= ed;
            acc3 = fmaf(env, pr*c3 - pi*s3, acc3);
        }
        float4 v = make_float4(acc0*ninv, acc1*ninv, acc2*ninv, acc3*ninv);
        *reinterpret_cast<float4*>(gout + tid*4) = v;
    }
}

// ---- K4: fused rc + sparse conv (Toeplitz, register window) + mix + tanh + out
__global__ void __launch_bounds__(256) k_conv(float* __restrict__ out, int out_size)
{
    int tid = threadIdx.x;
    int q   = tid & 127;
    int h   = tid >> 7;                 // half 0: r 0..7, half 1: r 8..15
    int p0  = blockIdx.x * 4;           // 4 frames per tile, grid 128

    __shared__ float rt_s[2][FRAMES];
    __shared__ float s_sum[4][128];
    __shared__ float s_cs[4][128];

    // deformation weights per cell (depend on n only)
    float dv0[4], dv1[4];
    #pragma unroll
    for (int j = 0; j < 4; ++j) {
        int n = ((p0 + j) << 7) + q;
        float cpos = __fsub_rn(__fmul_rn((float)n + 0.5f, 1.0f/256.0f), 0.5f);
        float fl = floorf(cpos);
        int   i0 = (int)fl;
        float w  = cpos - fl;
        int k0 = max(i0, 0);
        int k1 = min(i0 + 1, DEFF - 1);
        float w0 = 1.0f - w;
        dv0[j] = __fadd_rn(__fmul_rn(w0, d_dsm[k0]),        __fmul_rn(w, d_dsm[k1]));
        dv1[j] = __fadd_rn(__fmul_rn(w0, d_dsm[DEFF + k0]), __fmul_rn(w, d_dsm[DEFF + k1]));
    }

    float sum[4] = {0.f,0.f,0.f,0.f};
    float cs[4]  = {0.f,0.f,0.f,0.f};

    for (int rr = 0; rr < 8; ++rr) {
        int r = h*8 + rr;
        __syncthreads();
        for (int i = q; i < FRAMES; i += 128) rt_s[h][i] = d_routed[r*FRAMES + i];
        __syncthreads();

        // ---- rc: 16-tap sparse conv with impulse (f ascending == u descending)
        float arc[4] = {0.f,0.f,0.f,0.f};
        const float* impr = d_imp + r*WIN + q;
        #pragma unroll
        for (int u = 15; u >= 0; --u) {
            float iv = __ldg(impr + (u << 7));
            #pragma unroll
            for (int j = 0; j < 4; ++j) {
                int f = p0 + j - u;
                if (f >= 0) arc[j] = fmaf(rt_s[h][f], iv, arc[j]);
            }
        }

        // ---- conv taps on g (rows m descending => f ascending per cell) ----
        int Mcap   = (max(d_Lg[2*r], d_Lg[2*r + 1]) - 1) >> 7;
        int mstart = min(Mcap, p0 + 3);
        float a0[4] = {0.f,0.f,0.f,0.f};
        float a1[4] = {0.f,0.f,0.f,0.f};
        const float* g0 = d_g + (size_t)(2*r)*NS + q;
        const float* g1 = g0 + NS;
        float rtw[4];
        #pragma unroll
        for (int j = 0; j < 4; ++j) {
            int f = p0 + j - mstart;
            rtw[j] = (f >= 0) ? rt_s[h][f] : 0.f;
        }
        #pragma unroll 4
        for (int m = mstart; m >= 0; --m) {
            float v0 = __ldg(g0 + (m << 7));
            float v1 = __ldg(g1 + (m << 7));
            #pragma unroll
            for (int j = 0; j < 4; ++j) {
                a0[j] = fmaf(rtw[j], v0, a0[j]);
                a1[j] = fmaf(rtw[j], v1, a1[j]);
            }
            rtw[0] = rtw[1]; rtw[1] = rtw[2]; rtw[2] = rtw[3];
            int fn = p0 + 4 - m;                  // f for j=3 at next iter
            rtw[3] = (fn < FRAMES) ? rt_s[h][fn] : 0.f;
        }

        // ---- mix + tanh ----
        float m0v = d_m0[r], m1v = d_m1[r], gav = d_ga[r];
        #pragma unroll
        for (int j = 0; j < 4; ++j) {
            float x  = __fadd_rn(__fmul_rn(dv0[j], a0[j]), __fmul_rn(dv1[j], a1[j]));
            float x2 = __fadd_rn(__fmul_rn(m0v, arc[j]), __fmul_rn(m1v, x));
            sum[j] = __fadd_rn(sum[j], tanhf(__fmul_rn(x2, gav)));
            cs[j]  = __fadd_rn(cs[j], arc[j]);
        }
    }

    // combine the two r-halves and write outputs
    __syncthreads();
    if (h == 1) {
        #pragma unroll
        for (int j = 0; j < 4; ++j) { s_sum[j][q] = sum[j]; s_cs[j][q] = cs[j]; }
    }
    __syncthreads();
    if (h == 0) {
        #pragma unroll
        for (int j = 0; j < 4; ++j) {
            int n = ((p0 + j) << 7) + q;
            out[n] = __fadd_rn(sum[j], s_sum[j][q]);
            float C = __fadd_rn(cs[j], s_cs[j][q]);
            if (OC + n < out_size) out[OC + n] = C;
        }
    }
}

// ------------------------------------------------------------------------------
extern "C" void kernel_launch(void* const* d_in, const int* in_sizes, int n_in,
                              void* d_out, int out_size)
{
    const float* ctrl    = (const float*)d_in[0];
    const float* defo    = (const float*)d_in[1];
    const float* noise   = (const float*)d_in[2];
    const float* attack  = (const float*)d_in[3];
    const float* router  = (const float*)d_in[4];
    const float* mixp    = (const float*)d_in[5];
    const float* gains   = (const float*)d_in[6];
    const float* damping = (const float*)d_in[7];
    const float* mass    = (const float*)d_in[8];
    const float* tension = (const float*)d_in[9];
    const float* idisp   = (const float*)d_in[10];
    const float* amps    = (const float*)d_in[11];
    float* out = (float*)d_out;

    k_setup  <<<82, 512>>>(ctrl, defo, noise, attack, router, mixp, gains,
                           damping, mass, tension, idisp, amps, out, out_size);
    k_respref<<<dim3(272, 32), 256>>>();   // blocks 0..255: res; 256..271: prefactors
    k_g      <<<dim3(64, RE),  256>>>();   // bx<3: FIR head; else modal tail
    k_conv   <<<128, 256>>>(out, out_size);
}

// round 8
// speedup vs baseline: 1.3760x; 1.3760x over previous
#include <cuda_runtime.h>
#include <cuda_bf16.h>

#define NS      65536
#define NRES    16
#define NOSC    16
#define NCPD    16
#define WIN     2048
#define FRAMES  512
#define DEFF    256
#define RE      32            // NRES*NEXPR
#define ORE     512           // NOSC*NRES*NEXPR
#define OB      65536         // out offset: before_upsample
#define OC      73728         // out offset: cs
#define DELTA   (10.0f/65535.0f)
#define HEAD    3072          // direct-FIR head length (>= 2057, mult of 1024)
#define RESN    4096          // samples of d_res actually materialized (gfir reach)

// ----------------------------- device scratch --------------------------------
__device__ float d_xd[ORE], d_om[ORE], d_phi[ORE], d_aa[ORE], d_am[ORE];
__device__ float d_sc[ORE], d_sn[ORE], d_ed[ORE];   // per-mode step cos/sin, env step
__device__ int   d_nco[ORE];
__device__ int   d_Lg[RE], d_ncm[RE];
__device__ float d_routed[NRES*FRAMES];
__device__ float d_imp[NCPD*WIN];
__device__ float d_dsm[2*DEFF];
__device__ float d_m0[NRES], d_m1[NRES], d_ga[NRES];
__device__ float d_res[RE*RESN];   // un-normalized resonances, head only
__device__ float d_ssp[RE*256];    // sum-of-squares partials
__device__ float d_Pr[ORE], d_Pi[ORE];   // modal prefactors for g (UNscaled by ninv)
__device__ float d_g[RE*NS];       // g = (imp (*) res_normalized)
__device__ float d_rc[NCPD*NS];    // routed_c
__device__ float d_xv[NRES*NS];    // per-res tanh terms

// ------------------- K1: params, softmaxes, impulse, routing -----------------
__global__ void k_setup(const float* __restrict__ ctrl,  const float* __restrict__ defo,
                        const float* __restrict__ noise, const float* __restrict__ attack,
                        const float* __restrict__ router,const float* __restrict__ mixp,
                        const float* __restrict__ gains, const float* __restrict__ damping,
                        const float* __restrict__ mass,  const float* __restrict__ tension,
                        const float* __restrict__ idisp, const float* __restrict__ amps,
                        float* __restrict__ out, int out_size)
{
    int b = blockIdx.x, tid = threadIdx.x;
    if (b == 0) {
        // one thread per (osc,res,expr); flat idx = o*32 + r*2 + e
        __shared__ int snc[ORE];
        int idx = tid;
        float m   = 1.0f / (1.0f + expf(-mass[idx]));
        float dmp = (1.0f / (1.0f + expf(-damping[idx]))) * 30.0f;
        float ten = exp10f(tension[idx]);
        float x0  = idisp[idx];
        float xd  = dmp / (2.0f * m);
        float om2 = fmaxf(__fsub_rn(ten, __fmul_rn(xd, xd)), 1e-12f);
        float om  = sqrtf(om2);
        float phi = atan2f(__fmul_rn(xd, x0), __fmul_rn(x0, om));
        float a   = x0 / cosf(phi);
        float amp = amps[idx];
        float amp2 = __fmul_rn(amp, amp);
        d_xd[idx] = xd; d_om[idx] = om; d_phi[idx] = phi; d_aa[idx] = a; d_am[idx] = amp2;
        // rotation constants for the modal tail (double-accurate step)
        double bd = (double)om * (10.0 / 65535.0);
        d_sc[idx] = (float)cos(bd);
        d_sn[idx] = (float)sin(bd);
        d_ed[idx] = expf(-xd * DELTA);
        // truncation: coef*exp(-xd*t) < coef*e^-34 beyond tcut -> negligible
        float coef = fabsf(a) * amp2;
        float tcut = (logf(coef + 1e-30f) + 34.0f) / xd;
        int nc = (tcut <= 0.0f) ? 0 : (int)(tcut / DELTA) + 2;
        nc = min(nc, NS);
        d_nco[idx] = nc;
        snc[idx] = nc;
        __syncthreads();
        if (tid < RE) {
            int mx = 0;
            #pragma unroll
            for (int o = 0; o < NOSC; ++o) mx = max(mx, snc[o*RE + tid]);
            d_ncm[tid] = mx;
            d_Lg[tid]  = min(mx + WIN, NS);
        }
    } else if (b == 1) {
        if (tid < DEFF) {
            float v0 = 1.0f + defo[tid];
            float v1 = defo[DEFF + tid];
            float mx = fmaxf(v0, v1);
            float e0 = expf(v0 - mx), e1 = expf(v1 - mx);
            float inv = 1.0f / (e0 + e1);
            d_dsm[tid]        = e0 * inv;
            d_dsm[DEFF + tid] = e1 * inv;
        } else if (tid < DEFF + NRES) {
            int r = tid - DEFF;
            float a0 = mixp[r*2], a1 = mixp[r*2+1];
            float mx = fmaxf(a0, a1);
            float e0 = expf(a0 - mx), e1 = expf(a1 - mx);
            float inv = 1.0f / (e0 + e1);
            d_m0[r] = e0 * inv; d_m1[r] = e1 * inv;
            d_ga[r] = fabsf(gains[r]);
        }
    } else if (b < 66) {
        int i = (b - 2) * 512 + tid;                 // 0..32767
        d_imp[i] = attack[i] * noise[i];
    } else {
        int i = (b - 66) * 512 + tid;                // 0..8191
        int r = i >> 9, f = i & 511;
        float acc = 0.0f;
        #pragma unroll
        for (int c = 0; c < NCPD; ++c)
            acc = fmaf(ctrl[c*FRAMES + f], router[c*NRES + r], acc);
        d_routed[i] = acc;
        if (OB + i < out_size) out[OB + i] = acc;    // before_upsample output
    }
}

// ---- K2: (fused) resonances + SS partials  AND  modal prefactors ------------
__global__ void __launch_bounds__(256) k_respref()
{
    int tid = threadIdx.x;

    if (blockIdx.x >= 256) {
        // ---------------- prefactor part: one block per mode ----------------
        int w  = (blockIdx.x - 256) * 32 + blockIdx.y;   // mode 0..511
        int r  = (w & 31) >> 1;

        __shared__ float sb12, sbrest, sstepc, ssteps;
        if (tid == 0) {
            double beta_d = (double)d_om[w] * (10.0 / 65535.0);
            float b12 = __int_as_float(__float_as_int((float)beta_d) & 0xFFFFF000u);
            sb12   = b12;
            sbrest = (float)(beta_d - (double)b12);
            sstepc = (float)cos(beta_d);
            ssteps = (float)sin(beta_d);
        }
        __syncthreads();

        float xd = d_xd[w];
        float b12 = sb12, brest = sbrest, stepc = sstepc, steps = ssteps;

        const double TPd = 6.283185307179586476925287;
        const float  TPH = 6.28125f;
        const float  TPM = (float)(TPd - (double)TPH);
        const float  TPL = (float)(TPd - (double)TPH - (double)(float)(TPd - (double)TPH));
        const float  INV2PI = 0.15915494309189535f;

        int   k0 = tid * 8;
        float kf = (float)k0;
        float phi0 = kf * b12;                        // exact (8+12 mantissa bits)
        float qq = rintf(phi0 * INV2PI);
        float rp = fmaf(-qq, TPH, phi0);
        rp = fmaf(-qq, TPM, rp);
        rp = fmaf(-qq, TPL, rp);
        rp = fmaf(kf, brest, rp);
        float c, s;
        sincosf(rp, &s, &c);
        float env = expf(-xd * (kf * DELTA));
        float ef  = expf(-xd * DELTA);

        const float* impr = d_imp + r*WIN + (2047 - k0);
        float fr = 0.f, fi = 0.f;
        #pragma unroll
        for (int j = 0; j < 8; ++j) {
            float wgt = impr[-j] * env;
            fr = fmaf(wgt, c, fr);
            fi = fmaf(wgt, s, fi);
            float c2 = c*stepc - s*steps;
            float s2 = c*steps + s*stepc;
            c = c2; s = s2;
            env *= ef;
        }

        double sr = (double)fr, si = (double)fi;
        #pragma unroll
        for (int off = 16; off; off >>= 1) {
            sr += __shfl_down_sync(0xffffffffu, sr, off);
            si += __shfl_down_sync(0xffffffffu, si, off);
        }
        __shared__ double redr[8], redi[8];
        int wi = tid >> 5, lane = tid & 31;
        if (lane == 0) { redr[wi] = sr; redi[wi] = si; }
        __syncthreads();
        if (tid == 0) {
            double Sr = 0.0, Si = 0.0;
            #pragma unroll
            for (int i = 0; i < 8; ++i) { Sr += redr[i]; Si += redi[i]; }
            float phi = d_phi[w];
            float a   = d_aa[w], am = d_am[w];
            float cp = cosf(phi), sp = sinf(phi);
            float Ar =  a * am * cp;
            float Ai = -a * am * sp;          // A = a*amp^2 * e^{-i phi}
            float Cr = (float)Sr, Ci = (float)Si;
            d_Pr[w] = (Ar*Cr - Ai*Ci);        // unscaled; ninv applied downstream
            d_Pi[w] = (Ar*Ci + Ai*Cr);
        }
        return;
    }

    // -------------------- resonance part (blocks 0..255) ---------------------
    int re = blockIdx.y;
    int n  = blockIdx.x * 256 + tid;

    if (blockIdx.x * 256 >= d_ncm[re]) {             // whole block past all cutoffs
        if (tid == 0) d_ssp[re*256 + blockIdx.x] = 0.0f;
        return;
    }

    __shared__ float sxd[NOSC], som[NOSC], sphi[NOSC], sa[NOSC], sam[NOSC];
    __shared__ int   snc[NOSC];
    if (tid < NOSC) {
        int idx = tid * RE + re;
        sxd[tid] = d_xd[idx]; som[tid] = d_om[idx]; sphi[tid] = d_phi[idx];
        sa[tid]  = d_aa[idx]; sam[tid] = d_am[idx]; snc[tid]  = d_nco[idx];
    }
    __syncthreads();

    float t = __fmul_rn((float)n, DELTA);
    float acc = 0.0f;
    #pragma unroll
    for (int o = 0; o < NOSC; ++o) {
        if (n < snc[o]) {
            float env = expf(-__fmul_rn(sxd[o], t));
            float arg = __fsub_rn(__fmul_rn(som[o], t), sphi[o]);  // match ref rounding
            float z   = __fmul_rn(__fmul_rn(sa[o], env), cosf(arg));
            acc = __fadd_rn(acc, __fmul_rn(z, sam[o]));
        }
    }
    if (n < 10) acc = __fmul_rn(acc, __fmul_rn((float)n, 1.0f/9.0f));   // ramp
    if (blockIdx.x < RESN/256) d_res[re*RESN + n] = acc;   // only the FIR head is read

    __shared__ float red[256];
    red[tid] = acc * acc;
    __syncthreads();
    for (int s = 128; s > 0; s >>= 1) {
        if (tid < s) red[tid] += red[tid + s];
        __syncthreads();
    }
    if (tid == 0) d_ssp[re*256 + blockIdx.x] = red[0];
}

// ---- K3: g materialization (FIR head + modal tail), norm inlined ------------
__global__ void __launch_bounds__(256) k_g()
{
    int re  = blockIdx.y;
    int tid = threadIdx.x;
    int T0  = blockIdx.x * 1024;
    int Lg  = d_Lg[re];
    float* gout = d_g + re*NS + T0;

    if (T0 >= Lg) {                      // g numerically zero here
        #pragma unroll
        for (int k = 0; k < 4; ++k) gout[tid + k*256] = 0.0f;
        return;
    }

    // inline norm: reduce 256 SS partials -> ninv
    __shared__ float nred[256];
    __shared__ float sninv;
    nred[tid] = d_ssp[re*256 + tid];
    __syncthreads();
    for (int s = 128; s > 0; s >>= 1) {
        if (tid < s) nred[tid] += nred[tid + s];
        __syncthreads();
    }
    if (tid == 0) sninv = 1.0f / (sqrtf(nred[0]) + 1e-8f);
    __syncthreads();
    float ninv = sninv;

    if (blockIdx.x < HEAD/1024) {
        // -------- direct FIR head --------
        int r = re >> 1;
        __shared__ float imp_s[WIN];
        __shared__ float res_s[3072];
        for (int i = tid; i < WIN; i += 256) imp_s[i] = d_imp[r*WIN + i];
        for (int i = tid; i < 3072; i += 256) {
            int gi = T0 - 2047 + i;
            res_s[i] = (gi >= 0) ? d_res[re*RESN + gi] : 0.0f;
        }
        __syncthreads();

        int t0l = tid * 4;
        float a0 = 0.f, a1 = 0.f, a2 = 0.f, a3 = 0.f;
        #pragma unroll 8
        for (int j = 0; j < WIN; ++j) {
            float ij = imp_s[j];
            int bi = 2047 + t0l - j;
            a0 = fmaf(ij, res_s[bi    ], a0);
            a1 = fmaf(ij, res_s[bi + 1], a1);
            a2 = fmaf(ij, res_s[bi + 2], a2);
            a3 = fmaf(ij, res_s[bi + 3], a3);
        }
        gout[t0l    ] = a0 * ninv;
        gout[t0l + 1] = a1 * ninv;
        gout[t0l + 2] = a2 * ninv;
        gout[t0l + 3] = a3 * ninv;
    } else {
        // -------- modal tail: 4 consecutive samples per thread, rotation ----
        __shared__ float sxd[NOSC], som[NOSC], spr[NOSC], spi[NOSC];
        __shared__ float ssc[NOSC], ssn[NOSC], sed[NOSC];
        if (tid < NOSC) {
            int idx = tid * RE + re;
            sxd[tid] = d_xd[idx]; som[tid] = d_om[idx];
            spr[tid] = d_Pr[idx]; spi[tid] = d_Pi[idx];
            ssc[tid] = d_sc[idx]; ssn[tid] = d_sn[idx]; sed[tid] = d_ed[idx];
        }
        __syncthreads();

        int n0 = T0 + tid * 4;
        float tau0 = __fmul_rn((float)(n0 - 2047), DELTA);
        float acc0 = 0.f, acc1 = 0.f, acc2 = 0.f, acc3 = 0.f;
        #pragma unroll
        for (int o = 0; o < NOSC; ++o) {
            float s0, c0;
            sincosf(som[o] * tau0, &s0, &c0);
            float env = expf(-sxd[o] * tau0);
            float pr = spr[o], pi = spi[o];
            float sc = ssc[o], sn = ssn[o], ed = sed[o];
            acc0 = fmaf(env, pr*c0 - pi*s0, acc0);
            float c1 = c0*sc - s0*sn, s1 = c0*sn + s0*sc; env *= ed;
            acc1 = fmaf(env, pr*c1 - pi*s1, acc1);
            float c2 = c1*sc - s1*sn, s2 = c1*sn + s1*sc; env *= ed;
            acc2 = fmaf(env, pr*c2 - pi*s2, acc2);
            float c3 = c2*sc - s2*sn, s3 = c2*sn + s2*sc; env *= ed;
            acc3 = fmaf(env, pr*c3 - pi*s3, acc3);
        }
        float4 v = make_float4(acc0*ninv, acc1*ninv, acc2*ninv, acc3*ninv);
        *reinterpret_cast<float4*>(gout + tid*4) = v;
    }
}

// ---- K4: fused rc + Toeplitz conv + mix + tanh. grid (64 n-tiles, 16 r) -----
__global__ void __launch_bounds__(256) k_conv()
{
    int tid = threadIdx.x;
    int q   = tid & 127;
    int h   = tid >> 7;                  // half owns 4 frames
    int r   = blockIdx.y;
    int p0  = blockIdx.x * 8 + h * 4;    // first frame of this half

    __shared__ float rt_s[FRAMES];
    for (int i = tid; i < FRAMES; i += 256) rt_s[i] = d_routed[r*FRAMES + i];
    __syncthreads();

    // deformation weights per cell (depend on n only)
    float dv0[4], dv1[4];
    #pragma unroll
    for (int j = 0; j < 4; ++j) {
        int n = ((p0 + j) << 7) + q;
        float cpos = __fsub_rn(__fmul_rn((float)n + 0.5f, 1.0f/256.0f), 0.5f);
        float fl = floorf(cpos);
        int   i0 = (int)fl;
        float w  = cpos - fl;
        int k0 = max(i0, 0);
        int k1 = min(i0 + 1, DEFF - 1);
        float w0 = 1.0f - w;
        dv0[j] = __fadd_rn(__fmul_rn(w0, d_dsm[k0]),        __fmul_rn(w, d_dsm[k1]));
        dv1[j] = __fadd_rn(__fmul_rn(w0, d_dsm[DEFF + k0]), __fmul_rn(w, d_dsm[DEFF + k1]));
    }

    // ---- rc: 16-tap sparse conv with impulse (f ascending == u descending) --
    float arc[4] = {0.f,0.f,0.f,0.f};
    const float* impr = d_imp + r*WIN + q;
    #pragma unroll
    for (int u = 15; u >= 0; --u) {
        float iv = __ldg(impr + (u << 7));
        #pragma unroll
        for (int j = 0; j < 4; ++j) {
            int f = p0 + j - u;
            if (f >= 0) arc[j] = fmaf(rt_s[f], iv, arc[j]);
        }
    }

    // ---- conv taps on g (rows m descending => f ascending per cell) ---------
    int Mcap   = (max(d_Lg[2*r], d_Lg[2*r + 1]) - 1) >> 7;
    int mstart = min(Mcap, p0 + 3);
    float a0[4] = {0.f,0.f,0.f,0.f};
    float a1[4] = {0.f,0.f,0.f,0.f};
    const float* g0 = d_g + (size_t)(2*r)*NS + q;
    const float* g1 = g0 + NS;
    float rtw[4];
    #pragma unroll
    for (int j = 0; j < 4; ++j) {
        int f = p0 + j - mstart;
        rtw[j] = (f >= 0) ? rt_s[f] : 0.f;
    }
    #pragma unroll 4
    for (int m = mstart; m >= 0; --m) {
        float v0 = __ldg(g0 + (m << 7));
        float v1 = __ldg(g1 + (m << 7));
        #pragma unroll
        for (int j = 0; j < 4; ++j) {
            a0[j] = fmaf(rtw[j], v0, a0[j]);
            a1[j] = fmaf(rtw[j], v1, a1[j]);
        }
        rtw[0] = rtw[1]; rtw[1] = rtw[2]; rtw[2] = rtw[3];
        int fn = p0 + 4 - m;                  // f for j=3 at next iter (m-1)
        rtw[3] = ((unsigned)fn < FRAMES) ? rt_s[fn] : 0.f;
    }

    // ---- mix + tanh + store per-r terms ----
    float m0v = d_m0[r], m1v = d_m1[r], gav = d_ga[r];
    #pragma unroll
    for (int j = 0; j < 4; ++j) {
        int n = ((p0 + j) << 7) + q;
        float x  = __fadd_rn(__fmul_rn(dv0[j], a0[j]), __fmul_rn(dv1[j], a1[j]));
        float x2 = __fadd_rn(__fmul_rn(m0v, arc[j]), __fmul_rn(m1v, x));
        d_xv[r*NS + n] = tanhf(__fmul_rn(x2, gav));
        d_rc[r*NS + n] = arc[j];
    }
}

// -------------------- K5: final reductions over res / cpd --------------------
__global__ void __launch_bounds__(256) k_out(float* __restrict__ out, int out_size)
{
    int n = blockIdx.x * 256 + threadIdx.x;
    float s = 0.0f;
    #pragma unroll
    for (int r = 0; r < NRES; ++r) s = __fadd_rn(s, d_xv[r*NS + n]);
    float cs = 0.0f;
    #pragma unroll
    for (int c = 0; c < NCPD; ++c) cs = __fadd_rn(cs, d_rc[c*NS + n]);
    out[n] = s;
    if (OC + n < out_size) out[OC + n] = cs;
}

// ------------------------------------------------------------------------------
extern "C" void kernel_launch(void* const* d_in, const int* in_sizes, int n_in,
                              void* d_out, int out_size)
{
    const float* ctrl    = (const float*)d_in[0];
    const float* defo    = (const float*)d_in[1];
    const float* noise   = (const float*)d_in[2];
    const float* attack  = (const float*)d_in[3];
    const float* router  = (const float*)d_in[4];
    const float* mixp    = (const float*)d_in[5];
    const float* gains   = (const float*)d_in[6];
    const float* damping = (const float*)d_in[7];
    const float* mass    = (const float*)d_in[8];
    const float* tension = (const float*)d_in[9];
    const float* idisp   = (const float*)d_in[10];
    const float* amps    = (const float*)d_in[11];
    float* out = (float*)d_out;

    k_setup  <<<82, 512>>>(ctrl, defo, noise, attack, router, mixp, gains,
                           damping, mass, tension, idisp, amps, out, out_size);
    k_respref<<<dim3(272, 32), 256>>>();   // blocks 0..255: res; 256..271: prefactors
    k_g      <<<dim3(64, RE),  256>>>();   // bx<3: FIR head; else modal tail
    k_conv   <<<dim3(64, 16),  256>>>();   // 1024 blocks: (8-frame tile) x r
    k_out    <<<256, 256>>>(out, out_size);
}

// round 9
// speedup vs baseline: 1.4177x; 1.0303x over previous
#include <cuda_runtime.h>
#include <cuda_bf16.h>

#define NS      65536
#define NRES    16
#define NOSC    16
#define NCPD    16
#define WIN     2048
#define FRAMES  512
#define DEFF    256
#define RE      32            // NRES*NEXPR
#define ORE     512           // NOSC*NRES*NEXPR
#define OB      65536         // out offset: before_upsample
#define OC      73728         // out offset: cs
#define DELTA   (10.0f/65535.0f)
#define HEAD    3072          // direct-FIR head length (>= 2057, mult of 1024)
#define RESN    4096          // samples of d_res actually materialized

// ----------------------------- device scratch --------------------------------
__device__ float d_xd[ORE], d_om[ORE];
__device__ float d_sc[ORE], d_sn[ORE], d_ed[ORE];   // per-mode step cos/sin, env step
__device__ int   d_nco[ORE];
__device__ float d_res[RE*RESN];   // un-normalized resonances, head only
__device__ float d_ssp[RE*256];    // sum-of-squares partials
__device__ float d_Pr[ORE], d_Pi[ORE];   // modal prefactors for g (UNscaled by ninv)
__device__ float d_g[RE*NS];       // g = (imp (*) res_normalized)
__device__ float d_rc[NCPD*NS];    // routed_c
__device__ float d_xv[NRES*NS];    // per-res tanh terms

// ---------------- per-mode parameter math (matches reference rounding) -------
__device__ __forceinline__ void calc_params(
    int idx,
    const float* __restrict__ damping, const float* __restrict__ mass,
    const float* __restrict__ tension, const float* __restrict__ idisp,
    const float* __restrict__ amps,
    float& xd, float& om, float& phi, float& a, float& amp2, int& nc)
{
    float m   = 1.0f / (1.0f + expf(-mass[idx]));
    float dmp = (1.0f / (1.0f + expf(-damping[idx]))) * 30.0f;
    float ten = exp10f(tension[idx]);
    float x0  = idisp[idx];
    xd  = dmp / (2.0f * m);
    float om2 = fmaxf(__fsub_rn(ten, __fmul_rn(xd, xd)), 1e-12f);
    om  = sqrtf(om2);
    phi = atan2f(__fmul_rn(xd, x0), __fmul_rn(x0, om));
    a   = x0 / cosf(phi);
    float amp = amps[idx];
    amp2 = __fmul_rn(amp, amp);
    float coef = fabsf(a) * amp2;
    float tcut = (logf(coef + 1e-30f) + 34.0f) / xd;
    nc = (tcut <= 0.0f) ? 0 : (int)(tcut / DELTA) + 2;
    nc = min(nc, NS);
}

// ---- K1: resonances + SS partials (blocks 0..255) AND modal prefactors ------
__global__ void __launch_bounds__(256) k_respref(
    const float* __restrict__ damping, const float* __restrict__ mass,
    const float* __restrict__ tension, const float* __restrict__ idisp,
    const float* __restrict__ amps,
    const float* __restrict__ attack,  const float* __restrict__ noise)
{
    int tid = threadIdx.x;

    if (blockIdx.x >= 256) {
        // ---------------- prefactor part: one block per mode ----------------
        int w = (blockIdx.x - 256) * 32 + blockIdx.y;   // mode 0..511
        int r = (w & 31) >> 1;

        __shared__ float sp[5];   // b12, brest, stepc, steps, xd
        float phi_ = 0.f, a_ = 0.f, am_ = 0.f;
        if (tid == 0) {
            float xd0, om0; int nc0;
            calc_params(w, damping, mass, tension, idisp, amps,
                        xd0, om0, phi_, a_, am_, nc0);
            double bd = (double)om0 * (10.0 / 65535.0);
            float b12 = __int_as_float(__float_as_int((float)bd) & 0xFFFFF000u);
            sp[0] = b12;
            sp[1] = (float)(bd - (double)b12);
            sp[2] = (float)cos(bd);
            sp[3] = (float)sin(bd);
            sp[4] = xd0;
            d_xd[w] = xd0; d_om[w] = om0; d_nco[w] = nc0;
            d_sc[w] = (float)cos(bd); d_sn[w] = (float)sin(bd);
            d_ed[w] = expf(-xd0 * DELTA);
        }
        __syncthreads();
        float b12 = sp[0], brest = sp[1], stepc = sp[2], steps = sp[3], xd = sp[4];

        const double TPd = 6.283185307179586476925287;
        const float  TPH = 6.28125f;
        const float  TPM = (float)(TPd - (double)TPH);
        const float  TPL = (float)(TPd - (double)TPH - (double)(float)(TPd - (double)TPH));
        const float  INV2PI = 0.15915494309189535f;

        int   k0 = tid * 8;
        float kf = (float)k0;
        float phi0 = kf * b12;                        // exact (8+12 mantissa bits)
        float qq = rintf(phi0 * INV2PI);
        float rp = fmaf(-qq, TPH, phi0);
        rp = fmaf(-qq, TPM, rp);
        rp = fmaf(-qq, TPL, rp);
        rp = fmaf(kf, brest, rp);
        float c, s;
        sincosf(rp, &s, &c);
        float env = expf(-xd * (kf * DELTA));
        float ef  = expf(-xd * DELTA);

        int base = r*WIN + (2047 - k0);
        float fr = 0.f, fi = 0.f;
        #pragma unroll
        for (int j = 0; j < 8; ++j) {
            float wgt = attack[base - j] * noise[base - j] * env;
            fr = fmaf(wgt, c, fr);
            fi = fmaf(wgt, s, fi);
            float c2 = c*stepc - s*steps;
            float s2 = c*steps + s*stepc;
            c = c2; s = s2;
            env *= ef;
        }

        double sr = (double)fr, si = (double)fi;
        #pragma unroll
        for (int off = 16; off; off >>= 1) {
            sr += __shfl_down_sync(0xffffffffu, sr, off);
            si += __shfl_down_sync(0xffffffffu, si, off);
        }
        __shared__ double redr[8], redi[8];
        int wi = tid >> 5, lane = tid & 31;
        if (lane == 0) { redr[wi] = sr; redi[wi] = si; }
        __syncthreads();
        if (tid == 0) {
            double Sr = 0.0, Si = 0.0;
            #pragma unroll
            for (int i = 0; i < 8; ++i) { Sr += redr[i]; Si += redi[i]; }
            float cp = cosf(phi_), spn = sinf(phi_);
            float Ar =  a_ * am_ * cp;
            float Ai = -a_ * am_ * spn;       // A = a*amp^2 * e^{-i phi}
            float Cr = (float)Sr, Ci = (float)Si;
            d_Pr[w] = (Ar*Cr - Ai*Ci);        // unscaled; ninv applied downstream
            d_Pi[w] = (Ar*Ci + Ai*Cr);
        }
        return;
    }

    // -------------------- resonance part (blocks 0..255) ---------------------
    int re = blockIdx.y;
    int n  = blockIdx.x * 256 + tid;

    __shared__ float sxd[NOSC], som[NOSC], sphi[NOSC], sa[NOSC], sam[NOSC];
    __shared__ int   snc[NOSC], sncm;
    if (tid < NOSC) {
        int idx = tid * RE + re;
        float xd, om, phi, a, amp2; int nc;
        calc_params(idx, damping, mass, tension, idisp, amps, xd, om, phi, a, amp2, nc);
        sxd[tid] = xd; som[tid] = om; sphi[tid] = phi;
        sa[tid]  = a;  sam[tid] = amp2; snc[tid] = nc;
    }
    __syncthreads();
    if (tid == 0) {
        int mx = 0;
        #pragma unroll
        for (int o = 0; o < NOSC; ++o) mx = max(mx, snc[o]);
        sncm = mx;
    }
    __syncthreads();

    if (blockIdx.x * 256 >= sncm) {                  // whole block past all cutoffs
        if (tid == 0) d_ssp[re*256 + blockIdx.x] = 0.0f;
        return;
    }

    float t = __fmul_rn((float)n, DELTA);
    float acc = 0.0f;
    #pragma unroll
    for (int o = 0; o < NOSC; ++o) {
        if (n < snc[o]) {
            float env = expf(-__fmul_rn(sxd[o], t));
            float arg = __fsub_rn(__fmul_rn(som[o], t), sphi[o]);  // match ref rounding
            float z   = __fmul_rn(__fmul_rn(sa[o], env), cosf(arg));
            acc = __fadd_rn(acc, __fmul_rn(z, sam[o]));
        }
    }
    if (n < 10) acc = __fmul_rn(acc, __fmul_rn((float)n, 1.0f/9.0f));   // ramp
    if (blockIdx.x < RESN/256) d_res[re*RESN + n] = acc;   // only the FIR head is read

    __shared__ float red[256];
    red[tid] = acc * acc;
    __syncthreads();
    for (int s = 128; s > 0; s >>= 1) {
        if (tid < s) red[tid] += red[tid + s];
        __syncthreads();
    }
    if (tid == 0) d_ssp[re*256 + blockIdx.x] = red[0];
}

// ---- K2: g materialization (FIR head + modal tail), norm inlined ------------
__global__ void __launch_bounds__(256) k_g(
    const float* __restrict__ attack, const float* __restrict__ noise)
{
    int re  = blockIdx.y;
    int tid = threadIdx.x;
    int T0  = blockIdx.x * 1024;
    float* gout = d_g + re*NS + T0;

    // per-block Lg from d_nco
    __shared__ int snco[NOSC], sLgS;
    if (tid < NOSC) snco[tid] = d_nco[tid*RE + re];
    __syncthreads();
    if (tid == 0) {
        int mx = 0;
        #pragma unroll
        for (int o = 0; o < NOSC; ++o) mx = max(mx, snco[o]);
        sLgS = min(mx + WIN, NS);
    }
    __syncthreads();
    int Lg = sLgS;

    if (T0 >= Lg) {                      // g numerically zero here
        #pragma unroll
        for (int k = 0; k < 4; ++k) gout[tid + k*256] = 0.0f;
        return;
    }

    // inline norm: reduce 256 SS partials -> ninv
    __shared__ float nred[256];
    __shared__ float sninv;
    nred[tid] = d_ssp[re*256 + tid];
    __syncthreads();
    for (int s = 128; s > 0; s >>= 1) {
        if (tid < s) nred[tid] += nred[tid + s];
        __syncthreads();
    }
    if (tid == 0) sninv = 1.0f / (sqrtf(nred[0]) + 1e-8f);
    __syncthreads();
    float ninv = sninv;

    if (blockIdx.x < HEAD/1024) {
        // -------- direct FIR head --------
        int r = re >> 1;
        __shared__ float imp_s[WIN];
        __shared__ float res_s[3072];
        for (int i = tid; i < WIN; i += 256)
            imp_s[i] = attack[r*WIN + i] * noise[r*WIN + i];
        for (int i = tid; i < 3072; i += 256) {
            int gi = T0 - 2047 + i;
            res_s[i] = (gi >= 0) ? d_res[re*RESN + gi] : 0.0f;
        }
        __syncthreads();

        int t0l = tid * 4;
        float a0 = 0.f, a1 = 0.f, a2 = 0.f, a3 = 0.f;
        #pragma unroll 8
        for (int j = 0; j < WIN; ++j) {
            float ij = imp_s[j];
            int bi = 2047 + t0l - j;
            a0 = fmaf(ij, res_s[bi    ], a0);
            a1 = fmaf(ij, res_s[bi + 1], a1);
            a2 = fmaf(ij, res_s[bi + 2], a2);
            a3 = fmaf(ij, res_s[bi + 3], a3);
        }
        gout[t0l    ] = a0 * ninv;
        gout[t0l + 1] = a1 * ninv;
        gout[t0l + 2] = a2 * ninv;
        gout[t0l + 3] = a3 * ninv;
    } else {
        // -------- modal tail: 4 consecutive samples per thread, rotation ----
        __shared__ float sxd[NOSC], som[NOSC], spr[NOSC], spi[NOSC];
        __shared__ float ssc[NOSC], ssn[NOSC], sed[NOSC];
        if (tid < NOSC) {
            int idx = tid * RE + re;
            sxd[tid] = d_xd[idx]; som[tid] = d_om[idx];
            spr[tid] = d_Pr[idx]; spi[tid] = d_Pi[idx];
            ssc[tid] = d_sc[idx]; ssn[tid] = d_sn[idx]; sed[tid] = d_ed[idx];
        }
        __syncthreads();

        int n0 = T0 + tid * 4;
        float tau0 = __fmul_rn((float)(n0 - 2047), DELTA);
        float acc0 = 0.f, acc1 = 0.f, acc2 = 0.f, acc3 = 0.f;
        #pragma unroll
        for (int o = 0; o < NOSC; ++o) {
            if (n0 < snco[o] + WIN) {
                float s0, c0;
                sincosf(som[o] * tau0, &s0, &c0);
                float env = expf(-sxd[o] * tau0);
                float pr = spr[o], pi = spi[o];
                float sc = ssc[o], sn = ssn[o], ed = sed[o];
                acc0 = fmaf(env, pr*c0 - pi*s0, acc0);
                float c1 = c0*sc - s0*sn, s1 = c0*sn + s0*sc; env *= ed;
                acc1 = fmaf(env, pr*c1 - pi*s1, acc1);
                float c2 = c1*sc - s1*sn, s2 = c1*sn + s1*sc; env *= ed;
                acc2 = fmaf(env, pr*c2 - pi*s2, acc2);
                float c3 = c2*sc - s2*sn, s3 = c2*sn + s2*sc; env *= ed;
                acc3 = fmaf(env, pr*c3 - pi*s3, acc3);
            }
        }
        float4 v = make_float4(acc0*ninv, acc1*ninv, acc2*ninv, acc3*ninv);
        *reinterpret_cast<float4*>(gout + tid*4) = v;
    }
}

// ---- K3: routed (inline) + rc (inline imp) + gather conv + mix + tanh -------
__global__ void __launch_bounds__(256) k_conv(
    const float* __restrict__ ctrl,   const float* __restrict__ router,
    const float* __restrict__ mixp,   const float* __restrict__ gains,
    const float* __restrict__ defo,
    const float* __restrict__ attack, const float* __restrict__ noise,
    float* __restrict__ out, int out_size)
{
    int r   = blockIdx.y;
    int N0  = blockIdx.x * 512;
    int tid = threadIdx.x;

    __shared__ float rt_s[FRAMES];
    __shared__ float dsm_s[2*DEFF];
    __shared__ int   sncb[RE], sLgM;
    __shared__ float sm0, sm1, sga;

    // routed row r (same fmaf order as before); block x==0 emits before_upsample
    for (int i = tid; i < FRAMES; i += 256) {
        float acc = 0.0f;
        #pragma unroll
        for (int c = 0; c < NCPD; ++c)
            acc = fmaf(ctrl[c*FRAMES + i], router[c*NRES + r], acc);
        rt_s[i] = acc;
        if (blockIdx.x == 0) {
            int oi = OB + r*FRAMES + i;
            if (oi < out_size) out[oi] = acc;
        }
    }
    // deformation softmax (full table; 256 threads -> 256 frames)
    {
        float v0 = 1.0f + defo[tid];
        float v1 = defo[DEFF + tid];
        float mx = fmaxf(v0, v1);
        float e0 = expf(v0 - mx), e1 = expf(v1 - mx);
        float inv = 1.0f / (e0 + e1);
        dsm_s[tid]        = e0 * inv;
        dsm_s[DEFF + tid] = e1 * inv;
    }
    if (tid < RE) {
        int o = tid >> 1, e = tid & 1;
        sncb[tid] = d_nco[o*RE + 2*r + e];
    }
    if (tid == 32) {
        float a0 = mixp[r*2], a1 = mixp[r*2+1];
        float mx = fmaxf(a0, a1);
        float e0 = expf(a0 - mx), e1 = expf(a1 - mx);
        float inv = 1.0f / (e0 + e1);
        sm0 = e0 * inv; sm1 = e1 * inv; sga = fabsf(gains[r]);
    }
    __syncthreads();
    if (tid == 0) {
        int mx = 0;
        #pragma unroll
        for (int j = 0; j < RE; ++j) mx = max(mx, sncb[j]);
        sLgM = min(mx + WIN, NS);
    }
    __syncthreads();

    int LgM = sLgM;
    float m0v = sm0, m1v = sm1, gav = sga;
    const float* g0 = d_g + (size_t)(2*r)*NS;
    const float* g1 = g0 + NS;

    #pragma unroll
    for (int h = 0; h < 2; ++h) {
        int n = N0 + tid + h*256;
        // deformation weights via jax.image.resize linear (half-pixel, clamped)
        float cpos = __fsub_rn(__fmul_rn((float)n + 0.5f, 1.0f/256.0f), 0.5f);
        float fl = floorf(cpos);
        int   i0 = (int)fl;
        float w  = cpos - fl;
        int k0 = max(i0, 0);
        int k1 = min(i0 + 1, DEFF - 1);
        float w0 = 1.0f - w;
        float dv0 = __fadd_rn(__fmul_rn(w0, dsm_s[k0]),        __fmul_rn(w, dsm_s[k1]));
        float dv1 = __fadd_rn(__fmul_rn(w0, dsm_s[DEFF + k0]), __fmul_rn(w, dsm_s[DEFF + k1]));

        int fhi = n >> 7;
        // rc: 16-tap sparse conv with inline impulse
        int flo2 = max(0, (n - (WIN - 1) + 127) >> 7);
        float arc = 0.0f;
        for (int f = flo2; f <= fhi; ++f) {
            int ii = r*WIN + (n - (f << 7));
            arc = fmaf(rt_s[f], attack[ii] * noise[ii], arc);
        }
        // conv taps on g
        int flo = max(0, (n - LgM + 128) >> 7);
        float c0 = 0.f, c1 = 0.f;
        for (int f = flo; f <= fhi; ++f) {
            float rf = rt_s[f];
            int k = n - (f << 7);
            c0 = fmaf(rf, __ldg(g0 + k), c0);
            c1 = fmaf(rf, __ldg(g1 + k), c1);
        }
        float x  = __fadd_rn(__fmul_rn(dv0, c0), __fmul_rn(dv1, c1));
        float x2 = __fadd_rn(__fmul_rn(m0v, arc), __fmul_rn(m1v, x));
        d_xv[r*NS + n] = tanhf(__fmul_rn(x2, gav));
        d_rc[r*NS + n] = arc;
    }
}

// -------------------- K4: final reductions over res / cpd --------------------
__global__ void __launch_bounds__(256) k_out(float* __restrict__ out, int out_size)
{
    int n = blockIdx.x * 256 + threadIdx.x;
    float s = 0.0f;
    #pragma unroll
    for (int r = 0; r < NRES; ++r) s = __fadd_rn(s, d_xv[r*NS + n]);
    float cs = 0.0f;
    #pragma unroll
    for (int c = 0; c < NCPD; ++c) cs = __fadd_rn(cs, d_rc[c*NS + n]);
    out[n] = s;
    if (OC + n < out_size) out[OC + n] = cs;
}

// ------------------------------------------------------------------------------
extern "C" void kernel_launch(void* const* d_in, const int* in_sizes, int n_in,
                              void* d_out, int out_size)
{
    const float* ctrl    = (const float*)d_in[0];
    const float* defo    = (const float*)d_in[1];
    const float* noise   = (const float*)d_in[2];
    const float* attack  = (const float*)d_in[3];
    const float* router  = (const float*)d_in[4];
    const float* mixp    = (const float*)d_in[5];
    const float* gains   = (const float*)d_in[6];
    const float* damping = (const float*)d_in[7];
    const float* mass    = (const float*)d_in[8];
    const float* tension = (const float*)d_in[9];
    const float* idisp   = (const float*)d_in[10];
    const float* amps    = (const float*)d_in[11];
    float* out = (float*)d_out;

    k_respref<<<dim3(272, 32), 256>>>(damping, mass, tension, idisp, amps, attack, noise);
    k_g      <<<dim3(64, RE),  256>>>(attack, noise);
    k_conv   <<<dim3(128, NRES), 256>>>(ctrl, router, mixp, gains, defo, attack, noise,
                                        out, out_size);
    k_out    <<<256, 256>>>(out, out_size);
}

// round 11
// speedup vs baseline: 1.7377x; 1.2257x over previous
#include <cuda_runtime.h>
#include <cuda_bf16.h>

#define NS      65536
#define NRES    16
#define NOSC    16
#define NCPD    16
#define WIN     2048
#define FRAMES  512
#define DEFF    256
#define RE      32            // NRES*NEXPR
#define ORE     512           // NOSC*NRES*NEXPR
#define OB      65536         // out offset: before_upsample
#define OC      73728         // out offset: cs
#define DELTA   (10.0f/65535.0f)
#define HEAD    3072          // direct-FIR head length (>= 2057, mult of 1024)

// ----------------------------- device scratch --------------------------------
__device__ float d_xd[ORE], d_om[ORE], d_phi[ORE], d_aa[ORE], d_am[ORE];
__device__ float d_sc[ORE], d_sn[ORE], d_ed[ORE];   // per-mode step cos/sin, env step
__device__ int   d_nco[ORE];
__device__ int   d_Lg[RE], d_ncm[RE];
__device__ float d_routed[NRES*FRAMES];
__device__ float d_imp[NCPD*WIN];
__device__ float d_dsm[2*DEFF];
__device__ float d_m0[NRES], d_m1[NRES], d_ga[NRES];
__device__ float d_res[RE*NS];     // un-normalized resonances (zero past cutoff)
__device__ float d_ssp[RE*256];    // sum-of-squares partials
__device__ float d_ninv[RE];       // 1/(||res||+1e-8)
__device__ float d_Pr[ORE], d_Pi[ORE];   // modal prefactors for g (scaled by ninv)
__device__ float d_g[RE*NS];       // g = (imp (*) res_normalized)
__device__ float d_rc[NCPD*NS];    // routed_c
__device__ float d_xv[NRES*NS];    // per-res tanh terms

// ------------------- K1: params, softmaxes, impulse, routing -----------------
__global__ void k_setup(const float* __restrict__ ctrl,  const float* __restrict__ defo,
                        const float* __restrict__ noise, const float* __restrict__ attack,
                        const float* __restrict__ router,const float* __restrict__ mixp,
                        const float* __restrict__ gains, const float* __restrict__ damping,
                        const float* __restrict__ mass,  const float* __restrict__ tension,
                        const float* __restrict__ idisp, const float* __restrict__ amps,
                        float* __restrict__ out, int out_size)
{
    int b = blockIdx.x, tid = threadIdx.x;
    if (b == 0) {
        __shared__ int snc[ORE];
        int idx = tid;
        float m   = 1.0f / (1.0f + expf(-mass[idx]));
        float dmp = (1.0f / (1.0f + expf(-damping[idx]))) * 30.0f;
        float ten = exp10f(tension[idx]);
        float x0  = idisp[idx];
        float xd  = dmp / (2.0f * m);
        float om2 = fmaxf(__fsub_rn(ten, __fmul_rn(xd, xd)), 1e-12f);
        float om  = sqrtf(om2);
        float phi = atan2f(__fmul_rn(xd, x0), __fmul_rn(x0, om));
        float a   = x0 / cosf(phi);
        float amp = amps[idx];
        float amp2 = __fmul_rn(amp, amp);
        d_xd[idx] = xd; d_om[idx] = om; d_phi[idx] = phi; d_aa[idx] = a; d_am[idx] = amp2;
        double bd = (double)om * (10.0 / 65535.0);
        d_sc[idx] = (float)cos(bd);
        d_sn[idx] = (float)sin(bd);
        d_ed[idx] = expf(-xd * DELTA);
        float coef = fabsf(a) * amp2;
        float tcut = (logf(coef + 1e-30f) + 34.0f) / xd;
        int nc = (tcut <= 0.0f) ? 0 : (int)(tcut / DELTA) + 2;
        nc = min(nc, NS);
        d_nco[idx] = nc;
        snc[idx] = nc;
        __syncthreads();
        if (tid < RE) {
            int mx = 0;
            #pragma unroll
            for (int o = 0; o < NOSC; ++o) mx = max(mx, snc[o*RE + tid]);
            d_ncm[tid] = mx;
            d_Lg[tid]  = min(mx + WIN, NS);
        }
    } else if (b == 1) {
        if (tid < DEFF) {
            float v0 = 1.0f + defo[tid];
            float v1 = defo[DEFF + tid];
            float mx = fmaxf(v0, v1);
            float e0 = expf(v0 - mx), e1 = expf(v1 - mx);
            float inv = 1.0f / (e0 + e1);
            d_dsm[tid]        = e0 * inv;
            d_dsm[DEFF + tid] = e1 * inv;
        } else if (tid < DEFF + NRES) {
            int r = tid - DEFF;
            float a0 = mixp[r*2], a1 = mixp[r*2+1];
            float mx = fmaxf(a0, a1);
            float e0 = expf(a0 - mx), e1 = expf(a1 - mx);
            float inv = 1.0f / (e0 + e1);
            d_m0[r] = e0 * inv; d_m1[r] = e1 * inv;
            d_ga[r] = fabsf(gains[r]);
        }
    } else if (b < 66) {
        int i = (b - 2) * 512 + tid;                 // 0..32767
        d_imp[i] = attack[i] * noise[i];
    } else {
        int i = (b - 66) * 512 + tid;                // 0..8191
        int r = i >> 9, f = i & 511;
        float acc = 0.0f;
        #pragma unroll
        for (int c = 0; c < NCPD; ++c)
            acc = fmaf(ctrl[c*FRAMES + f], router[c*NRES + r], acc);
        d_routed[i] = acc;
        if (OB + i < out_size) out[OB + i] = acc;    // before_upsample output
    }
}

// -------------- K2: materialize resonances + sum-of-squares partials ---------
__global__ void __launch_bounds__(256) k_res()
{
    int re  = blockIdx.y;
    int tid = threadIdx.x;
    int n   = blockIdx.x * 256 + tid;

    __shared__ float sxd[NOSC], som[NOSC], sphi[NOSC], sa[NOSC], sam[NOSC];
    __shared__ int   snc[NOSC];
    if (tid < NOSC) {
        int idx = tid * RE + re;
        sxd[tid] = d_xd[idx]; som[tid] = d_om[idx]; sphi[tid] = d_phi[idx];
        sa[tid]  = d_aa[idx]; sam[tid] = d_am[idx]; snc[tid]  = d_nco[idx];
    }
    __syncthreads();

    float t = __fmul_rn((float)n, DELTA);
    float acc = 0.0f;
    #pragma unroll
    for (int o = 0; o < NOSC; ++o) {
        if (n < snc[o]) {
            float env = expf(-__fmul_rn(sxd[o], t));
            float arg = __fsub_rn(__fmul_rn(som[o], t), sphi[o]);  // match ref rounding
            float z   = __fmul_rn(__fmul_rn(sa[o], env), cosf(arg));
            acc = __fadd_rn(acc, __fmul_rn(z, sam[o]));
        }
    }
    if (n < 10) acc = __fmul_rn(acc, __fmul_rn((float)n, 1.0f/9.0f));   // ramp
    d_res[re*NS + n] = acc;

    __shared__ float red[256];
    red[tid] = acc * acc;
    __syncthreads();
    for (int s = 128; s > 0; s >>= 1) {
        if (tid < s) red[tid] += red[tid + s];
        __syncthreads();
    }
    if (tid == 0) d_ssp[re*256 + blockIdx.x] = red[0];
}

// ----------------------------- K3: 1/(norm+1e-8) -----------------------------
__global__ void k_norm()
{
    int re = blockIdx.x, tid = threadIdx.x;
    __shared__ float red[256];
    red[tid] = d_ssp[re*256 + tid];
    __syncthreads();
    for (int s = 128; s > 0; s >>= 1) {
        if (tid < s) red[tid] += red[tid + s];
        __syncthreads();
    }
    if (tid == 0) d_ninv[re] = 1.0f / (sqrtf(red[0]) + 1e-8f);
}

// ------- K3b: modal prefactors  P_o = ninv * A_o * sum_j imp[j] e^{s(2047-j)D}
__global__ void __launch_bounds__(256) k_pref()
{
    int w   = blockIdx.x;            // mode 0..511
    int tid = threadIdx.x;
    int re  = w & 31;
    int r   = re >> 1;

    __shared__ float sb12, sbrest, sstepc, ssteps;
    if (tid == 0) {
        double beta_d = (double)d_om[w] * (10.0 / 65535.0);
        float b12 = __int_as_float(__float_as_int((float)beta_d) & 0xFFFFF000u);
        sb12   = b12;
        sbrest = (float)(beta_d - (double)b12);
        sstepc = (float)cos(beta_d);
        ssteps = (float)sin(beta_d);
    }
    __syncthreads();

    float xd = d_xd[w];
    float b12 = sb12, brest = sbrest, stepc = sstepc, steps = ssteps;

    const double TPd = 6.283185307179586476925287;
    const float  TPH = 6.28125f;
    const float  TPM = (float)(TPd - (double)TPH);
    const float  TPL = (float)(TPd - (double)TPH - (double)(float)(TPd - (double)TPH));
    const float  INV2PI = 0.15915494309189535f;

    int   k0 = tid * 8;
    float kf = (float)k0;
    float phi0 = kf * b12;                        // exact (8+12 mantissa bits)
    float q  = rintf(phi0 * INV2PI);
    float rp = fmaf(-q, TPH, phi0);               // q*TPH exact
    rp = fmaf(-q, TPM, rp);
    rp = fmaf(-q, TPL, rp);
    rp = fmaf(kf, brest, rp);
    float c, s;
    sincosf(rp, &s, &c);
    float env = expf(-xd * (kf * DELTA));
    float ef  = expf(-xd * DELTA);

    const float* impr = d_imp + r*WIN + (2047 - k0);
    float fr = 0.f, fi = 0.f;
    #pragma unroll
    for (int j = 0; j < 8; ++j) {
        float wgt = impr[-j] * env;
        fr = fmaf(wgt, c, fr);
        fi = fmaf(wgt, s, fi);
        float c2 = c*stepc - s*steps;             // rotate by beta
        float s2 = c*steps + s*stepc;
        c = c2; s = s2;
        env *= ef;
    }

    double sr = (double)fr, si = (double)fi;
    #pragma unroll
    for (int off = 16; off; off >>= 1) {
        sr += __shfl_down_sync(0xffffffffu, sr, off);
        si += __shfl_down_sync(0xffffffffu, si, off);
    }
    __shared__ double redr[8], redi[8];
    int wi = tid >> 5, lane = tid & 31;
    if (lane == 0) { redr[wi] = sr; redi[wi] = si; }
    __syncthreads();
    if (tid == 0) {
        double Sr = 0.0, Si = 0.0;
        #pragma unroll
        for (int i = 0; i < 8; ++i) { Sr += redr[i]; Si += redi[i]; }
        float phi = d_phi[w];
        float a   = d_aa[w], am = d_am[w];
        float cp = cosf(phi), sp = sinf(phi);
        float Ar =  a * am * cp;
        float Ai = -a * am * sp;          // A = a*amp^2 * e^{-i phi}
        float ninv = d_ninv[re];
        float Cr = (float)Sr, Ci = (float)Si;
        d_Pr[w] = (Ar*Cr - Ai*Ci) * ninv;
        d_Pi[w] = (Ar*Ci + Ai*Cr) * ninv;
    }
}

// -------------- K4a: direct FIR head of g (n < HEAD only) --------------------
__global__ void __launch_bounds__(256) k_gfir()
{
    int re = blockIdx.y;
    int r  = re >> 1;
    int T0 = blockIdx.x * 1024;
    int Lg = d_Lg[re];
    float* gout = d_g + re*NS + T0;

    if (T0 >= Lg) {
        #pragma unroll
        for (int k = 0; k < 4; ++k) gout[threadIdx.x + k*256] = 0.0f;
        return;
    }

    __shared__ float imp_s[WIN];
    __shared__ float res_s[3072];
    int tid = threadIdx.x;
    for (int i = tid; i < WIN; i += 256) imp_s[i] = d_imp[r*WIN + i];
    for (int i = tid; i < 3072; i += 256) {
        int gi = T0 - 2047 + i;
        res_s[i] = (gi >= 0) ? d_res[re*NS + gi] : 0.0f;
    }
    __syncthreads();

    float ninv = d_ninv[re];
    int t0l = tid * 4;
    float a0 = 0.f, a1 = 0.f, a2 = 0.f, a3 = 0.f;
    #pragma unroll 8
    for (int j = 0; j < WIN; ++j) {
        float ij = imp_s[j];
        int bi = 2047 + t0l - j;
        a0 = fmaf(ij, res_s[bi    ], a0);
        a1 = fmaf(ij, res_s[bi + 1], a1);
        a2 = fmaf(ij, res_s[bi + 2], a2);
        a3 = fmaf(ij, res_s[bi + 3], a3);
    }
    gout[t0l    ] = a0 * ninv;
    gout[t0l + 1] = a1 * ninv;
    gout[t0l + 2] = a2 * ninv;
    gout[t0l + 3] = a3 * ninv;
}

// -------------- K4b: modal tail of g — 32 samples/thread, phasor rotation ----
// smem load + barrier happen BEFORE any early exit (fix for R10 bug: loader
// threads could exit on n0>=Lg leaving smem uninitialized for live threads).
__global__ void __launch_bounds__(256) k_gmod()
{
    int re  = blockIdx.y;
    int tid = threadIdx.x;
    int T0  = HEAD + blockIdx.x * 8192;
    int n0  = T0 + tid * 32;

    __shared__ float sxd[NOSC], som[NOSC], spr[NOSC], spi[NOSC];
    __shared__ float ssc[NOSC], ssn[NOSC], sed[NOSC];
    __shared__ int   sgc[NOSC];
    if (tid < NOSC) {
        int idx = tid * RE + re;
        sxd[tid] = d_xd[idx]; som[tid] = d_om[idx];
        spr[tid] = d_Pr[idx]; spi[tid] = d_Pi[idx];
        ssc[tid] = d_sc[idx]; ssn[tid] = d_sn[idx]; sed[tid] = d_ed[idx];
        sgc[tid] = d_nco[idx] + WIN;     // per-mode g support
    }
    __syncthreads();

    if (n0 >= NS) return;
    int Lg  = d_Lg[re];
    float* gp = d_g + re*NS + n0;

    if (n0 >= Lg) {                      // g numerically zero here
        #pragma unroll
        for (int j = 0; j < 32; j += 4)
            *reinterpret_cast<float4*>(gp + j) = make_float4(0.f, 0.f, 0.f, 0.f);
        return;
    }

    float acc[32];
    #pragma unroll
    for (int j = 0; j < 32; ++j) acc[j] = 0.f;

    float tau0 = __fmul_rn((float)(n0 - 2047), DELTA);
    #pragma unroll
    for (int o = 0; o < NOSC; ++o) {
        if (n0 < sgc[o]) {               // skip fully-negligible modes
            float s, c;
            sincosf(som[o] * tau0, &s, &c);
            float env = expf(-sxd[o] * tau0);
            float pr = spr[o], pi = spi[o];
            float sc = ssc[o], sn = ssn[o], ed = sed[o];
            #pragma unroll
            for (int j = 0; j < 32; ++j) {
                acc[j] = fmaf(env, pr*c - pi*s, acc[j]);
                float c2 = c*sc - s*sn;  // rotate phase by beta
                float s2 = c*sn + s*sc;
                c = c2; s = s2;
                env *= ed;               // advance envelope
            }
        }
    }
    #pragma unroll
    for (int j = 0; j < 32; j += 4)
        *reinterpret_cast<float4*>(gp + j) = make_float4(acc[j], acc[j+1], acc[j+2], acc[j+3]);
}

// ------------------ K5: routed_c (16-tap sparse convolution) -----------------
__global__ void __launch_bounds__(256) k_rc()
{
    int c = blockIdx.y;
    int n = blockIdx.x * 256 + threadIdx.x;
    int fhi = n >> 7;
    int flo = max(0, (n - (WIN - 1) + 127) >> 7);
    const float* rt = d_routed + c*FRAMES;
    const float* im = d_imp    + c*WIN;
    float acc = 0.0f;
    for (int f = flo; f <= fhi; ++f)
        acc = fmaf(rt[f], im[n - (f << 7)], acc);
    d_rc[c*NS + n] = acc;
}

// -------- K6: conv-apply (sparse taps on g), deform mix, res mix, tanh -------
__global__ void __launch_bounds__(256) k_conv()
{
    int r  = blockIdx.y;
    int N0 = blockIdx.x * 512;
    int tid = threadIdx.x;

    __shared__ float rt_s[FRAMES];
    for (int i = tid; i < FRAMES; i += 256) rt_s[i] = d_routed[r*FRAMES + i];
    __syncthreads();

    const float* g0 = d_g + (2*r)*NS;
    const float* g1 = g0 + NS;
    int LgM = max(d_Lg[2*r], d_Lg[2*r + 1]);
    float m0v = d_m0[r], m1v = d_m1[r], gav = d_ga[r];

    #pragma unroll
    for (int h = 0; h < 2; ++h) {
        int n = N0 + tid + h*256;
        float cpos = __fsub_rn(__fmul_rn((float)n + 0.5f, 1.0f/256.0f), 0.5f);
        float fl = floorf(cpos);
        int   i0 = (int)fl;
        float w  = cpos - fl;
        int k0 = max(i0, 0);
        int k1 = min(i0 + 1, DEFF - 1);
        float w0 = 1.0f - w;
        float dv0 = __fadd_rn(__fmul_rn(w0, d_dsm[k0]),        __fmul_rn(w, d_dsm[k1]));
        float dv1 = __fadd_rn(__fmul_rn(w0, d_dsm[DEFF + k0]), __fmul_rn(w, d_dsm[DEFF + k1]));

        int fhi = n >> 7;
        int flo = max(0, (n - LgM + 128) >> 7);
        float c0 = 0.f, c1 = 0.f;
        for (int f = flo; f <= fhi; ++f) {
            float rf = rt_s[f];
            int k = n - (f << 7);
            c0 = fmaf(rf, __ldg(g0 + k), c0);
            c1 = fmaf(rf, __ldg(g1 + k), c1);
        }
        float x  = __fadd_rn(__fmul_rn(dv0, c0), __fmul_rn(dv1, c1));
        float rc = d_rc[r*NS + n];
        float x2 = __fadd_rn(__fmul_rn(m0v, rc), __fmul_rn(m1v, x));
        d_xv[r*NS + n] = tanhf(__fmul_rn(x2, gav));
    }
}

// -------------------- K7: final reductions over res / cpd --------------------
__global__ void __launch_bounds__(256) k_out(float* __restrict__ out, int out_size)
{
    int n = blockIdx.x * 256 + threadIdx.x;
    float s = 0.0f;
    #pragma unroll
    for (int r = 0; r < NRES; ++r) s = __fadd_rn(s, d_xv[r*NS + n]);
    float cs = 0.0f;
    #pragma unroll
    for (int c = 0; c < NCPD; ++c) cs = __fadd_rn(cs, d_rc[c*NS + n]);
    out[n] = s;
    if (OC + n < out_size) out[OC + n] = cs;
}

// ------------------------------------------------------------------------------
extern "C" void kernel_launch(void* const* d_in, const int* in_sizes, int n_in,
                              void* d_out, int out_size)
{
    const float* ctrl    = (const float*)d_in[0];
    const float* defo    = (const float*)d_in[1];
    const float* noise   = (const float*)d_in[2];
    const float* attack  = (const float*)d_in[3];
    const float* router  = (const float*)d_in[4];
    const float* mixp    = (const float*)d_in[5];
    const float* gains   = (const float*)d_in[6];
    const float* damping = (const float*)d_in[7];
    const float* mass    = (const float*)d_in[8];
    const float* tension = (const float*)d_in[9];
    const float* idisp   = (const float*)d_in[10];
    const float* amps    = (const float*)d_in[11];
    float* out = (float*)d_out;

    k_setup<<<82, 512>>>(ctrl, defo, noise, attack, router, mixp, gains,
                         damping, mass, tension, idisp, amps, out, out_size);
    k_res  <<<dim3(256, RE),   256>>>();
    k_norm <<<RE,              256>>>();
    k_pref <<<ORE,             256>>>();
    k_gfir <<<dim3(HEAD/1024, RE), 256>>>();
    k_gmod <<<dim3(8, RE),     256>>>();      // 32 samples/thread, phasor rotation
    k_rc   <<<dim3(256, NCPD), 256>>>();
    k_conv <<<dim3(128, NRES), 256>>>();
    k_out  <<<256,             256>>>(out, out_size);
}